// round 16
// baseline (speedup 1.0000x reference)
#include <cuda_runtime.h>
#include <cuda_fp16.h>
#include <cstdint>
#include <cstring>

#define N_NODES 12288
#define DIM 256
#define KCL 16
#define KW 256               // plain fp16 W, K = 256
#define NIT (KW / 32)        // 8
#define CAP 128              // per-node edge bucket capacity
#define STAGES 4
#define NTILES ((N_NODES / 64) * (DIM / 128))   // 384 GEMM tiles
#define NGRP (N_NODES / 64)                     // 192 row groups
#define CAB (N_NODES / 8)                       // 1536 convA blocks (8 rows each)
#define FB_CT 384                               // fill blocks (4 edges/thr, E=393216)

// ctrl layout: [0:16) colsumsq | [16] loss ticket | [17] wcnt | [18,18+NGRP) acnt
#define CTRL_RED 0
#define CTRL_TICKET 16
#define CTRL_WCNT 17
#define CTRL_ACNT 18
#define CTRL_SIZE (18 + NGRP)

// ---- static device scratch ----
__device__ __half g_t[N_NODES * DIM];                // GEMM output, fp16
__device__ __half g_a[N_NODES * DIM];                // GEMM input (fp16 x, then fp16 h)
__device__ __half g_w1[KW * DIM];                    // [256,256] fp16
__device__ __half g_w2[KW * DIM];
__device__ int   g_deg[N_NODES];
__device__ int2  g_bucket[N_NODES * CAP];            // (src, bits(w))
__device__ int   g_ctrl[CTRL_SIZE];                  // zeroed by memset each launch

// ================= PTX helpers =================
__device__ __forceinline__ uint32_t smem_u32(const void* p) {
    uint32_t a;
    asm("{ .reg .u64 t; cvta.to.shared.u64 t, %1; cvt.u32.u64 %0, t; }" : "=r"(a) : "l"(p));
    return a;
}
#define CP_ASYNC16(sa, gp) \
    asm volatile("cp.async.cg.shared.global [%0], [%1], 16;" :: "r"(sa), "l"(gp))
#define CP_COMMIT() asm volatile("cp.async.commit_group;" ::: "memory")
#define CP_WAIT(n)  asm volatile("cp.async.wait_group %0;" :: "n"(n) : "memory")

#define LDSM4(r0, r1, r2, r3, a) \
    asm volatile("ldmatrix.sync.aligned.m8n8.x4.shared.b16 {%0,%1,%2,%3}, [%4];" \
                 : "=r"(r0), "=r"(r1), "=r"(r2), "=r"(r3) : "r"(a))
#define LDSM2T(r0, r1, a) \
    asm volatile("ldmatrix.sync.aligned.m8n8.x2.trans.shared.b16 {%0,%1}, [%2];" \
                 : "=r"(r0), "=r"(r1) : "r"(a))
#define MMA16816H(c, a, b) \
    asm volatile("mma.sync.aligned.m16n8k16.row.col.f32.f16.f16.f32 " \
                 "{%0,%1,%2,%3}, {%4,%5,%6,%7}, {%8,%9}, {%0,%1,%2,%3};" \
                 : "+f"((c)[0]), "+f"((c)[1]), "+f"((c)[2]), "+f"((c)[3]) \
                 : "r"((a)[0]), "r"((a)[1]), "r"((a)[2]), "r"((a)[3]), \
                   "r"((b)[0]), "r"((b)[1]))

__device__ __forceinline__ uint32_t h2_pack(float a, float b) {
    __half2 t = __floats2half2_rn(a, b);
    uint32_t u;
    memcpy(&u, &t, 4);
    return u;
}

// ================= GEMM tile body (shared) =================
#define APITCH 40
#define BPITCH 136
#define A_ST (64 * APITCH)
#define B_ST (32 * BPITCH)
#define SMEM_MMA (STAGES * (A_ST + B_ST) * 2)

__device__ __forceinline__ void gemm_tile(__half* dsm,
                                          const __half* __restrict__ Ah,
                                          const __half* __restrict__ Wh,
                                          __half* __restrict__ C,
                                          int bm, int bn, int tid) {
    __half* As = dsm;
    __half* Bs = dsm + STAGES * A_ST;
    int warp = tid >> 5, lane = tid & 31;
    int wr = warp >> 2, wc = warp & 3;

    float acc[2][4][4];
#pragma unroll
    for (int i = 0; i < 2; i++)
#pragma unroll
        for (int j = 0; j < 4; j++)
#pragma unroll
            for (int f = 0; f < 4; f++) acc[i][j][f] = 0.f;

    int ar = tid >> 2, ac = (tid & 3) * 8;
    int br = tid >> 4, bc = (tid & 15) * 8;

    uint32_t sA0 = smem_u32(&As[ar * APITCH + ac]);
    uint32_t sB0 = smem_u32(&Bs[br * BPITCH + bc]);
    uint32_t sB1 = smem_u32(&Bs[(br + 16) * BPITCH + bc]);
    uint32_t lA0 = smem_u32(&As[(wr * 32 + (lane & 15)) * APITCH + ((lane >> 4) << 3)]);
    uint32_t lB0 = smem_u32(&Bs[(lane & 15) * BPITCH + wc * 32]);

    const __half* gA = Ah + (size_t)(bm + ar) * DIM + ac;   // + k0
    const __half* gB = Wh + (size_t)br * DIM + bn + bc;     // + k0 * DIM

#define LOAD_TILE(i, slot)                                                   \
    do {                                                                     \
        int k0 = (i) * 32;                                                   \
        const __half* ga = gA + k0;                                          \
        const __half* gb = gB + (size_t)k0 * DIM;                            \
        CP_ASYNC16(sA0 + (slot) * (A_ST * 2), ga);                           \
        CP_ASYNC16(sB0 + (slot) * (B_ST * 2), gb);                           \
        CP_ASYNC16(sB1 + (slot) * (B_ST * 2), gb + 16 * DIM);                \
    } while (0)

    LOAD_TILE(0, 0); CP_COMMIT();
    LOAD_TILE(1, 1); CP_COMMIT();
    LOAD_TILE(2, 2); CP_COMMIT();

    int slot = 0, pslot = 3;
    for (int i = 0; i < NIT; i++) {
        CP_WAIT(2);
        __syncthreads();
        if (i + 3 < NIT) LOAD_TILE(i + 3, pslot);
        CP_COMMIT();
        uint32_t lA = lA0 + slot * (A_ST * 2);
        uint32_t lB = lB0 + slot * (B_ST * 2);
#pragma unroll
        for (int kt = 0; kt < 2; kt++) {
            uint32_t a[2][4];
#pragma unroll
            for (int mt = 0; mt < 2; mt++)
                LDSM4(a[mt][0], a[mt][1], a[mt][2], a[mt][3],
                      lA + (mt * 16 * APITCH + kt * 16) * 2);
            uint32_t b[4][2];
#pragma unroll
            for (int nt = 0; nt < 4; nt++)
                LDSM2T(b[nt][0], b[nt][1], lB + (kt * 16 * BPITCH + nt * 8) * 2);
#pragma unroll
            for (int mt = 0; mt < 2; mt++)
#pragma unroll
                for (int nt = 0; nt < 4; nt++) MMA16816H(acc[mt][nt], a[mt], b[nt]);
        }
        if (++slot == STAGES) slot = 0;
        if (++pslot == STAGES) pslot = 0;
    }

#pragma unroll
    for (int mt = 0; mt < 2; mt++)
#pragma unroll
        for (int nt = 0; nt < 4; nt++) {
            int row = bm + wr * 32 + mt * 16 + (lane >> 2);
            int col = bn + wc * 32 + nt * 8 + (lane & 3) * 2;
            *(__half2*)&C[(size_t)row * DIM + col] =
                __floats2half2_rn(acc[mt][nt][0], acc[mt][nt][1]);
            *(__half2*)&C[(size_t)(row + 8) * DIM + col] =
                __floats2half2_rn(acc[mt][nt][2], acc[mt][nt][3]);
        }
}

// ====== front kernel: convW1 | convA | convW2 | fill | GEMM1 tiles (spin-wait) ======
// bids: [0,32) convW1 -> wcnt | [32,32+CAB) convA -> acnt[grp] | [+32) convW2
//       [+FB_CT) fill | [+NTILES) GEMM tiles (wait wcnt==32 && acnt[grp]==8)
#define B_W1 0
#define B_CA 32
#define B_W2 (B_CA + CAB)
#define B_FI (B_W2 + 32)
#define B_GE (B_FI + FB_CT)

__global__ __launch_bounds__(256, 3) void k_front(const float* __restrict__ x,
                                                  const float* __restrict__ W1,
                                                  const float* __restrict__ W2,
                                                  const int* __restrict__ src,
                                                  const int* __restrict__ dst,
                                                  const float* __restrict__ ew,
                                                  __half* __restrict__ C) {
    extern __shared__ __align__(16) __half dsm[];
    int b = blockIdx.x, tid = threadIdx.x;
    if (b < B_CA) {
        // convW1: 32 blocks
        int idx = (b * 256 + tid) * 8;
        float4 v0 = *(const float4*)(W1 + idx);
        float4 v1 = *(const float4*)(W1 + idx + 4);
        *(uint4*)&g_w1[idx] = make_uint4(h2_pack(v0.x, v0.y), h2_pack(v0.z, v0.w),
                                         h2_pack(v1.x, v1.y), h2_pack(v1.z, v1.w));
        __threadfence();
        __syncthreads();
        if (tid == 0) atomicAdd(&g_ctrl[CTRL_WCNT], 1);
    } else if (b < B_W2) {
        // convA: 1536 blocks, 8 rows each
        int rel = b - B_CA;
        int idx = (rel * 256 + tid) * 8;
        float4 v0 = *(const float4*)(x + idx);
        float4 v1 = *(const float4*)(x + idx + 4);
        *(uint4*)&g_a[idx] = make_uint4(h2_pack(v0.x, v0.y), h2_pack(v0.z, v0.w),
                                        h2_pack(v1.x, v1.y), h2_pack(v1.z, v1.w));
        __threadfence();
        __syncthreads();
        if (tid == 0) atomicAdd(&g_ctrl[CTRL_ACNT + (rel >> 3)], 1);
    } else if (b < B_FI) {
        // convW2: 32 blocks (consumed by next kernel; no counter)
        int rel = b - B_W2;
        int idx = (rel * 256 + tid) * 8;
        float4 v0 = *(const float4*)(W2 + idx);
        float4 v1 = *(const float4*)(W2 + idx + 4);
        *(uint4*)&g_w2[idx] = make_uint4(h2_pack(v0.x, v0.y), h2_pack(v0.z, v0.w),
                                         h2_pack(v1.x, v1.y), h2_pack(v1.z, v1.w));
    } else if (b < B_GE) {
        // bucket fill: 4 edges/thread (deg pre-zeroed by memset)
        int e = ((b - B_FI) * 256 + tid) * 4;
        int4 s4 = *(const int4*)(src + e);
        int4 d4 = *(const int4*)(dst + e);
        float4 w4 = *(const float4*)(ew + e);
        int p;
        p = atomicAdd(&g_deg[d4.x], 1);
        if (p < CAP) g_bucket[(size_t)d4.x * CAP + p] = make_int2(s4.x, __float_as_int(w4.x));
        p = atomicAdd(&g_deg[d4.y], 1);
        if (p < CAP) g_bucket[(size_t)d4.y * CAP + p] = make_int2(s4.y, __float_as_int(w4.y));
        p = atomicAdd(&g_deg[d4.z], 1);
        if (p < CAP) g_bucket[(size_t)d4.z * CAP + p] = make_int2(s4.z, __float_as_int(w4.z));
        p = atomicAdd(&g_deg[d4.w], 1);
        if (p < CAP) g_bucket[(size_t)d4.w * CAP + p] = make_int2(s4.w, __float_as_int(w4.w));
    } else {
        // GEMM1 tile: wait on W1 + its 64-row A group, then compute
        int t = b - B_GE;
        int grp = t >> 1;
        if (tid == 0) {
            while (atomicAdd(&g_ctrl[CTRL_WCNT], 0) < 32) __nanosleep(100);
            while (atomicAdd(&g_ctrl[CTRL_ACNT + grp], 0) < 8) __nanosleep(100);
        }
        __syncthreads();
        __threadfence();
        gemm_tile(dsm, g_a, g_w1, C, grp * 64, (t & 1) * 128, tid);
    }
}

// ================= plain mma layer 2 =================
__global__ __launch_bounds__(256, 3) void k_mma(const __half* __restrict__ Ah,
                                                const __half* __restrict__ Wh,
                                                __half* __restrict__ C) {
    extern __shared__ __align__(16) __half dsm[];
    int b = blockIdx.x;
    gemm_tile(dsm, Ah, Wh, C, (b >> 1) * 64, (b & 1) * 128, threadIdx.x);
}

// ================= gather core: warp-per-node, lane owns cols [8l, 8l+8), fp16 t =================
__device__ __forceinline__ void gather_node(const __half* __restrict__ t,
                                            const float* __restrict__ bias,
                                            int node, int lane,
                                            float4& a0, float4& a1) {
    a0 = *(const float4*)&bias[8 * lane];
    a1 = *(const float4*)&bias[8 * lane + 4];
    int cnt = min(g_deg[node], CAP);
    const int2* bk = g_bucket + (size_t)node * CAP;
    for (int j0 = 0; j0 < cnt; j0 += 32) {
        int2 e = make_int2(0, 0);
        if (j0 + lane < cnt) e = bk[j0 + lane];
        int m = min(32, cnt - j0);
#pragma unroll 4
        for (int j = 0; j < m; j++) {
            int s = __shfl_sync(0xffffffffu, e.x, j);
            float w = __int_as_float(__shfl_sync(0xffffffffu, e.y, j));
            uint4 v = *(const uint4*)(t + (size_t)s * DIM + 8 * lane);
            float2 f0 = __half22float2(*(__half2*)&v.x);
            float2 f1 = __half22float2(*(__half2*)&v.y);
            float2 f2 = __half22float2(*(__half2*)&v.z);
            float2 f3 = __half22float2(*(__half2*)&v.w);
            a0.x += w * f0.x; a0.y += w * f0.y; a0.z += w * f1.x; a0.w += w * f1.y;
            a1.x += w * f2.x; a1.y += w * f2.y; a1.z += w * f3.x; a1.w += w * f3.y;
        }
    }
    a0.x = fmaxf(a0.x, 0.f); a0.y = fmaxf(a0.y, 0.f);
    a0.z = fmaxf(a0.z, 0.f); a0.w = fmaxf(a0.w, 0.f);
    a1.x = fmaxf(a1.x, 0.f); a1.y = fmaxf(a1.y, 0.f);
    a1.z = fmaxf(a1.z, 0.f); a1.w = fmaxf(a1.w, 0.f);
}

// ================= agg layer 1: gather + relu -> fp16 =================
__global__ __launch_bounds__(256) void k_agg1(const __half* __restrict__ t,
                                              const float* __restrict__ bias,
                                              __half* __restrict__ outh) {
    int warp = threadIdx.x >> 5, lane = threadIdx.x & 31;
    int node = blockIdx.x * 8 + warp;
    float4 a0, a1;
    gather_node(t, bias, node, lane, a0, a1);
    *(uint4*)&outh[(size_t)node * DIM + 8 * lane] =
        make_uint4(h2_pack(a0.x, a0.y), h2_pack(a0.z, a0.w),
                   h2_pack(a1.x, a1.y), h2_pack(a1.z, a1.w));
}

// ================= fused agg2 + MLP + softmax + colsumsq + loss (ticket) =================
__global__ __launch_bounds__(512) void k_aggmlp(const __half* __restrict__ t,
                                                const float* __restrict__ bias,
                                                const float* __restrict__ Wm,
                                                const float* __restrict__ bm,
                                                float* __restrict__ out,
                                                float* __restrict__ out_loss, int Nn) {
    __shared__ float sW[KCL * DIM];
    __shared__ float sh[16][DIM];
    __shared__ float part[16][KCL];
    __shared__ float sbm[KCL];
    int tid = threadIdx.x;
    for (int idx = tid; idx < KCL * DIM; idx += 512)
        sW[idx] = Wm[(idx & 255) * KCL + (idx >> 8)];
    if (tid < KCL) sbm[tid] = bm[tid];

    int warp = tid >> 5, lane = tid & 31;
    int node = blockIdx.x * 16 + warp;
    float4 a0, a1;
    gather_node(t, bias, node, lane, a0, a1);
    *(float4*)&sh[warp][8 * lane] = a0;
    *(float4*)&sh[warp][8 * lane + 4] = a1;
    __syncthreads();

    float acc[KCL];
#pragma unroll
    for (int k = 0; k < KCL; k++) acc[k] = 0.f;
#pragma unroll
    for (int m = 0; m < 8; m++) {
        float hv = sh[warp][lane + 32 * m];
#pragma unroll
        for (int k = 0; k < KCL; k++) acc[k] += hv * sW[k * DIM + lane + 32 * m];
    }
#pragma unroll
    for (int off = 16; off >= 1; off >>= 1)
#pragma unroll
        for (int k = 0; k < KCL; k++) acc[k] += __shfl_xor_sync(0xffffffffu, acc[k], off);

    float* red = (float*)&g_ctrl[CTRL_RED];
    if (lane < KCL) {
        float logit = acc[lane] + sbm[lane];
        float mx = logit;
#pragma unroll
        for (int off = 8; off >= 1; off >>= 1) mx = fmaxf(mx, __shfl_xor_sync(0xffffu, mx, off));
        float e = expf(logit - mx);
        float se = e;
#pragma unroll
        for (int off = 8; off >= 1; off >>= 1) se += __shfl_xor_sync(0xffffu, se, off);
        float sv = e / se;
        out[(size_t)node * KCL + lane] = sv;
        part[warp][lane] = sv * sv;
    }
    __syncthreads();
    if (tid < KCL) {
        float s = 0.f;
#pragma unroll
        for (int w = 0; w < 16; w++) s += part[w][tid];
        atomicAdd(&red[tid], s);
    }
    __syncthreads();
    if (tid == 0) {
        __threadfence();
        int prev = atomicAdd(&g_ctrl[CTRL_TICKET], 1);
        if (prev == (int)gridDim.x - 1) {
            float L = 0.f;
#pragma unroll
            for (int k = 0; k < KCL; k++) L += sqrtf(red[k] + 1e-15f);
            *out_loss = -L / sqrtf((float)Nn * (float)KCL);
        }
    }
}

// ================= launch =================
extern "C" void kernel_launch(void* const* d_in, const int* in_sizes, int n_in,
                              void* d_out, int out_size) {
    const float* x  = (const float*)d_in[0];
    const float* ew = (const float*)d_in[1];
    const float* W1 = (const float*)d_in[2];
    const float* b1 = (const float*)d_in[3];
    const float* W2 = (const float*)d_in[4];
    const float* b2 = (const float*)d_in[5];
    const float* Wm = (const float*)d_in[6];
    const float* bm = (const float*)d_in[7];
    const int*   ei = (const int*)d_in[8];

    int Nn = in_sizes[0] / DIM;
    int E  = in_sizes[1];
    const int* src = ei;
    const int* dst = ei + E;
    float* out = (float*)d_out;

    __half *t_buf, *a_buf, *w2_buf;
    int *deg_buf, *ctrl_buf;
    cudaGetSymbolAddress((void**)&t_buf, g_t);
    cudaGetSymbolAddress((void**)&a_buf, g_a);
    cudaGetSymbolAddress((void**)&w2_buf, g_w2);
    cudaGetSymbolAddress((void**)&deg_buf, g_deg);
    cudaGetSymbolAddress((void**)&ctrl_buf, g_ctrl);

    cudaFuncSetAttribute(k_front, cudaFuncAttributeMaxDynamicSharedMemorySize, SMEM_MMA);
    cudaFuncSetAttribute(k_mma,   cudaFuncAttributeMaxDynamicSharedMemorySize, SMEM_MMA);

    cudaMemsetAsync(deg_buf, 0, N_NODES * sizeof(int));
    cudaMemsetAsync(ctrl_buf, 0, CTRL_SIZE * sizeof(int));

    // front: convW1 + convA + convW2 + fill + layer-1 GEMM (spin-synced)
    k_front<<<B_GE + NTILES, 256, SMEM_MMA>>>(x, W1, W2, src, dst, ew, t_buf);
    k_agg1<<<Nn / 8, 256>>>(t_buf, b1, a_buf);
    k_mma<<<NTILES, 256, SMEM_MMA>>>(a_buf, w2_buf, t_buf);
    k_aggmlp<<<Nn / 16, 512>>>(t_buf, b2, Wm, bm, out, out + (out_size - 1), Nn);
}

// round 17
// speedup vs baseline: 1.1312x; 1.1312x over previous
#include <cuda_runtime.h>
#include <cuda_fp16.h>
#include <cstdint>
#include <cstring>

#define N_NODES 12288
#define DIM 256
#define KCL 16
#define KW 256               // plain fp16 W, K = 256
#define NIT (KW / 32)        // 8
#define CAP 128              // per-node edge bucket capacity
#define STAGES 4
#define NTILES ((N_NODES / 64) * (DIM / 128))   // 384 GEMM tiles

// ---- static device scratch ----
__device__ __half g_t[N_NODES * DIM];                // GEMM output, fp16
__device__ __half g_a[N_NODES * DIM];                // GEMM input (fp16 x, then fp16 h)
__device__ __half g_w1[KW * DIM];                    // [256,256] fp16
__device__ __half g_w2[KW * DIM];
__device__ int   g_deg[N_NODES];
__device__ int2  g_bucket[N_NODES * CAP];            // (src, bits(w))
__device__ float g_red[KCL + 1];                     // [0:16) colsumsq, [16] ticket

// ================= PTX helpers =================
__device__ __forceinline__ uint32_t smem_u32(const void* p) {
    uint32_t a;
    asm("{ .reg .u64 t; cvta.to.shared.u64 t, %1; cvt.u32.u64 %0, t; }" : "=r"(a) : "l"(p));
    return a;
}
#define CP_ASYNC16(sa, gp) \
    asm volatile("cp.async.cg.shared.global [%0], [%1], 16;" :: "r"(sa), "l"(gp))
#define CP_COMMIT() asm volatile("cp.async.commit_group;" ::: "memory")
#define CP_WAIT(n)  asm volatile("cp.async.wait_group %0;" :: "n"(n) : "memory")

#define LDSM4(r0, r1, r2, r3, a) \
    asm volatile("ldmatrix.sync.aligned.m8n8.x4.shared.b16 {%0,%1,%2,%3}, [%4];" \
                 : "=r"(r0), "=r"(r1), "=r"(r2), "=r"(r3) : "r"(a))
#define LDSM2T(r0, r1, a) \
    asm volatile("ldmatrix.sync.aligned.m8n8.x2.trans.shared.b16 {%0,%1}, [%2];" \
                 : "=r"(r0), "=r"(r1) : "r"(a))
#define MMA16816H(c, a, b) \
    asm volatile("mma.sync.aligned.m16n8k16.row.col.f32.f16.f16.f32 " \
                 "{%0,%1,%2,%3}, {%4,%5,%6,%7}, {%8,%9}, {%0,%1,%2,%3};" \
                 : "+f"((c)[0]), "+f"((c)[1]), "+f"((c)[2]), "+f"((c)[3]) \
                 : "r"((a)[0]), "r"((a)[1]), "r"((a)[2]), "r"((a)[3]), \
                   "r"((b)[0]), "r"((b)[1]))

__device__ __forceinline__ uint32_t h2_pack(float a, float b) {
    __half2 t = __floats2half2_rn(a, b);
    uint32_t u;
    memcpy(&u, &t, 4);
    return u;
}

// ================= GEMM tile body (shared by both mma kernels) =================
#define APITCH 40
#define BPITCH 136
#define A_ST (64 * APITCH)
#define B_ST (32 * BPITCH)
#define SMEM_MMA (STAGES * (A_ST + B_ST) * 2)

__device__ __forceinline__ void gemm_tile(__half* dsm,
                                          const __half* __restrict__ Ah,
                                          const __half* __restrict__ Wh,
                                          __half* __restrict__ C,
                                          int bm, int bn, int tid) {
    __half* As = dsm;
    __half* Bs = dsm + STAGES * A_ST;
    int warp = tid >> 5, lane = tid & 31;
    int wr = warp >> 2, wc = warp & 3;

    float acc[2][4][4];
#pragma unroll
    for (int i = 0; i < 2; i++)
#pragma unroll
        for (int j = 0; j < 4; j++)
#pragma unroll
            for (int f = 0; f < 4; f++) acc[i][j][f] = 0.f;

    int ar = tid >> 2, ac = (tid & 3) * 8;
    int br = tid >> 4, bc = (tid & 15) * 8;

    uint32_t sA0 = smem_u32(&As[ar * APITCH + ac]);
    uint32_t sB0 = smem_u32(&Bs[br * BPITCH + bc]);
    uint32_t sB1 = smem_u32(&Bs[(br + 16) * BPITCH + bc]);
    uint32_t lA0 = smem_u32(&As[(wr * 32 + (lane & 15)) * APITCH + ((lane >> 4) << 3)]);
    uint32_t lB0 = smem_u32(&Bs[(lane & 15) * BPITCH + wc * 32]);

    const __half* gA = Ah + (size_t)(bm + ar) * DIM + ac;   // + k0
    const __half* gB = Wh + (size_t)br * DIM + bn + bc;     // + k0 * DIM

#define LOAD_TILE(i, slot)                                                   \
    do {                                                                     \
        int k0 = (i) * 32;                                                   \
        const __half* ga = gA + k0;                                          \
        const __half* gb = gB + (size_t)k0 * DIM;                            \
        CP_ASYNC16(sA0 + (slot) * (A_ST * 2), ga);                           \
        CP_ASYNC16(sB0 + (slot) * (B_ST * 2), gb);                           \
        CP_ASYNC16(sB1 + (slot) * (B_ST * 2), gb + 16 * DIM);                \
    } while (0)

    LOAD_TILE(0, 0); CP_COMMIT();
    LOAD_TILE(1, 1); CP_COMMIT();
    LOAD_TILE(2, 2); CP_COMMIT();

    int slot = 0, pslot = 3;
    for (int i = 0; i < NIT; i++) {
        CP_WAIT(2);
        __syncthreads();
        if (i + 3 < NIT) LOAD_TILE(i + 3, pslot);
        CP_COMMIT();
        uint32_t lA = lA0 + slot * (A_ST * 2);
        uint32_t lB = lB0 + slot * (B_ST * 2);
#pragma unroll
        for (int kt = 0; kt < 2; kt++) {
            uint32_t a[2][4];
#pragma unroll
            for (int mt = 0; mt < 2; mt++)
                LDSM4(a[mt][0], a[mt][1], a[mt][2], a[mt][3],
                      lA + (mt * 16 * APITCH + kt * 16) * 2);
            uint32_t b[4][2];
#pragma unroll
            for (int nt = 0; nt < 4; nt++)
                LDSM2T(b[nt][0], b[nt][1], lB + (kt * 16 * BPITCH + nt * 8) * 2);
#pragma unroll
            for (int mt = 0; mt < 2; mt++)
#pragma unroll
                for (int nt = 0; nt < 4; nt++) MMA16816H(acc[mt][nt], a[mt], b[nt]);
        }
        if (++slot == STAGES) slot = 0;
        if (++pslot == STAGES) pslot = 0;
    }

#pragma unroll
    for (int mt = 0; mt < 2; mt++)
#pragma unroll
        for (int nt = 0; nt < 4; nt++) {
            int row = bm + wr * 32 + mt * 16 + (lane >> 2);
            int col = bn + wc * 32 + nt * 8 + (lane & 3) * 2;
            *(__half2*)&C[(size_t)row * DIM + col] =
                __floats2half2_rn(acc[mt][nt][0], acc[mt][nt][1]);
            *(__half2*)&C[(size_t)(row + 8) * DIM + col] =
                __floats2half2_rn(acc[mt][nt][2], acc[mt][nt][3]);
        }
}

// ================= mega prologue: zero-state + convW1 + convA =================
// blocks: [0,12) zero deg (+red in block 0) | [12,44) W1 | [44,44+1536) x->fp16
__global__ __launch_bounds__(256) void k_mega(const float* __restrict__ x,
                                              const float* __restrict__ W1) {
    int b = blockIdx.x, tid = threadIdx.x;
    if (b < 12) {
        int i = (b * 256 + tid) * 4;
        *(int4*)&g_deg[i] = make_int4(0, 0, 0, 0);
        if (b == 0 && tid <= KCL) g_red[tid] = 0.f;
    } else if (b < 44) {
        int rel = b - 12;
        int idx = (rel * 256 + tid) * 8;
        float4 v0 = *(const float4*)(W1 + idx);
        float4 v1 = *(const float4*)(W1 + idx + 4);
        *(uint4*)&g_w1[idx] = make_uint4(h2_pack(v0.x, v0.y), h2_pack(v0.z, v0.w),
                                         h2_pack(v1.x, v1.y), h2_pack(v1.z, v1.w));
    } else {
        int idx = ((b - 44) * 256 + tid) * 8;
        float4 v0 = *(const float4*)(x + idx);
        float4 v1 = *(const float4*)(x + idx + 4);
        *(uint4*)&g_a[idx] = make_uint4(h2_pack(v0.x, v0.y), h2_pack(v0.z, v0.w),
                                        h2_pack(v1.x, v1.y), h2_pack(v1.z, v1.w));
    }
}

// ================= fused mma layer 1 + bucket fill + convW2 (heterogeneous blocks) ======
// [0, NTILES): GEMM tiles | [NTILES, NTILES+FB): fill 4 edges/thr | rest: convW2 (32 blks)
__global__ __launch_bounds__(256, 3) void k_mma1(const __half* __restrict__ Ah,
                                                 const __half* __restrict__ Wh,
                                                 __half* __restrict__ C,
                                                 const int* __restrict__ src,
                                                 const int* __restrict__ dst,
                                                 const float* __restrict__ ew,
                                                 const float* __restrict__ W2,
                                                 int FB) {
    extern __shared__ __align__(16) __half dsm[];
    int b = blockIdx.x, tid = threadIdx.x;
    if (b < NTILES) {
        gemm_tile(dsm, Ah, Wh, C, (b >> 1) * 64, (b & 1) * 128, tid);
    } else if (b < NTILES + FB) {
        int e = ((b - NTILES) * 256 + tid) * 4;
        int4 s4 = *(const int4*)(src + e);
        int4 d4 = *(const int4*)(dst + e);
        float4 w4 = *(const float4*)(ew + e);
        int p;
        p = atomicAdd(&g_deg[d4.x], 1);
        if (p < CAP) g_bucket[(size_t)d4.x * CAP + p] = make_int2(s4.x, __float_as_int(w4.x));
        p = atomicAdd(&g_deg[d4.y], 1);
        if (p < CAP) g_bucket[(size_t)d4.y * CAP + p] = make_int2(s4.y, __float_as_int(w4.y));
        p = atomicAdd(&g_deg[d4.z], 1);
        if (p < CAP) g_bucket[(size_t)d4.z * CAP + p] = make_int2(s4.z, __float_as_int(w4.z));
        p = atomicAdd(&g_deg[d4.w], 1);
        if (p < CAP) g_bucket[(size_t)d4.w * CAP + p] = make_int2(s4.w, __float_as_int(w4.w));
    } else {
        int rel = b - NTILES - FB;   // 0..31
        int idx = (rel * 256 + tid) * 8;
        float4 v0 = *(const float4*)(W2 + idx);
        float4 v1 = *(const float4*)(W2 + idx + 4);
        *(uint4*)&g_w2[idx] = make_uint4(h2_pack(v0.x, v0.y), h2_pack(v0.z, v0.w),
                                         h2_pack(v1.x, v1.y), h2_pack(v1.z, v1.w));
    }
}

// ================= plain mma layer 2 =================
__global__ __launch_bounds__(256, 3) void k_mma(const __half* __restrict__ Ah,
                                                const __half* __restrict__ Wh,
                                                __half* __restrict__ C) {
    extern __shared__ __align__(16) __half dsm[];
    int b = blockIdx.x;
    gemm_tile(dsm, Ah, Wh, C, (b >> 1) * 64, (b & 1) * 128, threadIdx.x);
}

// ================= gather core: warp-per-node, lane owns cols [8l, 8l+8), fp16 t =================
__device__ __forceinline__ void gather_node(const __half* __restrict__ t,
                                            const float* __restrict__ bias,
                                            int node, int lane,
                                            float4& a0, float4& a1) {
    a0 = *(const float4*)&bias[8 * lane];
    a1 = *(const float4*)&bias[8 * lane + 4];
    int cnt = min(g_deg[node], CAP);
    const int2* bk = g_bucket + (size_t)node * CAP;
    for (int j0 = 0; j0 < cnt; j0 += 32) {
        int2 e = make_int2(0, 0);
        if (j0 + lane < cnt) e = bk[j0 + lane];
        int m = min(32, cnt - j0);
#pragma unroll 4
        for (int j = 0; j < m; j++) {
            int s = __shfl_sync(0xffffffffu, e.x, j);
            float w = __int_as_float(__shfl_sync(0xffffffffu, e.y, j));
            uint4 v = *(const uint4*)(t + (size_t)s * DIM + 8 * lane);
            float2 f0 = __half22float2(*(__half2*)&v.x);
            float2 f1 = __half22float2(*(__half2*)&v.y);
            float2 f2 = __half22float2(*(__half2*)&v.z);
            float2 f3 = __half22float2(*(__half2*)&v.w);
            a0.x += w * f0.x; a0.y += w * f0.y; a0.z += w * f1.x; a0.w += w * f1.y;
            a1.x += w * f2.x; a1.y += w * f2.y; a1.z += w * f3.x; a1.w += w * f3.y;
        }
    }
    a0.x = fmaxf(a0.x, 0.f); a0.y = fmaxf(a0.y, 0.f);
    a0.z = fmaxf(a0.z, 0.f); a0.w = fmaxf(a0.w, 0.f);
    a1.x = fmaxf(a1.x, 0.f); a1.y = fmaxf(a1.y, 0.f);
    a1.z = fmaxf(a1.z, 0.f); a1.w = fmaxf(a1.w, 0.f);
}

// ================= agg layer 1: gather + relu -> fp16 =================
__global__ __launch_bounds__(256) void k_agg1(const __half* __restrict__ t,
                                              const float* __restrict__ bias,
                                              __half* __restrict__ outh) {
    int warp = threadIdx.x >> 5, lane = threadIdx.x & 31;
    int node = blockIdx.x * 8 + warp;
    float4 a0, a1;
    gather_node(t, bias, node, lane, a0, a1);
    *(uint4*)&outh[(size_t)node * DIM + 8 * lane] =
        make_uint4(h2_pack(a0.x, a0.y), h2_pack(a0.z, a0.w),
                   h2_pack(a1.x, a1.y), h2_pack(a1.z, a1.w));
}

// ================= fused agg2 + MLP + softmax + colsumsq + loss (ticket) =================
__global__ __launch_bounds__(512) void k_aggmlp(const __half* __restrict__ t,
                                                const float* __restrict__ bias,
                                                const float* __restrict__ Wm,
                                                const float* __restrict__ bm,
                                                float* __restrict__ out,
                                                float* __restrict__ out_loss, int Nn) {
    __shared__ float sW[KCL * DIM];
    __shared__ float sh[16][DIM];
    __shared__ float part[16][KCL];
    __shared__ float sbm[KCL];
    int tid = threadIdx.x;
    for (int idx = tid; idx < KCL * DIM; idx += 512)
        sW[idx] = Wm[(idx & 255) * KCL + (idx >> 8)];
    if (tid < KCL) sbm[tid] = bm[tid];

    int warp = tid >> 5, lane = tid & 31;
    int node = blockIdx.x * 16 + warp;
    float4 a0, a1;
    gather_node(t, bias, node, lane, a0, a1);
    *(float4*)&sh[warp][8 * lane] = a0;
    *(float4*)&sh[warp][8 * lane + 4] = a1;
    __syncthreads();

    float acc[KCL];
#pragma unroll
    for (int k = 0; k < KCL; k++) acc[k] = 0.f;
#pragma unroll
    for (int m = 0; m < 8; m++) {
        float hv = sh[warp][lane + 32 * m];
#pragma unroll
        for (int k = 0; k < KCL; k++) acc[k] += hv * sW[k * DIM + lane + 32 * m];
    }
#pragma unroll
    for (int off = 16; off >= 1; off >>= 1)
#pragma unroll
        for (int k = 0; k < KCL; k++) acc[k] += __shfl_xor_sync(0xffffffffu, acc[k], off);

    if (lane < KCL) {
        float logit = acc[lane] + sbm[lane];
        float mx = logit;
#pragma unroll
        for (int off = 8; off >= 1; off >>= 1) mx = fmaxf(mx, __shfl_xor_sync(0xffffu, mx, off));
        float e = expf(logit - mx);
        float se = e;
#pragma unroll
        for (int off = 8; off >= 1; off >>= 1) se += __shfl_xor_sync(0xffffu, se, off);
        float sv = e / se;
        out[(size_t)node * KCL + lane] = sv;
        part[warp][lane] = sv * sv;
    }
    __syncthreads();
    if (tid < KCL) {
        float s = 0.f;
#pragma unroll
        for (int w = 0; w < 16; w++) s += part[w][tid];
        atomicAdd(&g_red[tid], s);
    }
    __syncthreads();
    if (tid == 0) {
        __threadfence();
        int prev = atomicAdd((int*)&g_red[KCL], 1);
        if (prev == (int)gridDim.x - 1) {
            float L = 0.f;
#pragma unroll
            for (int k = 0; k < KCL; k++) L += sqrtf(g_red[k] + 1e-15f);
            *out_loss = -L / sqrtf((float)Nn * (float)KCL);
        }
    }
}

// ================= launch =================
extern "C" void kernel_launch(void* const* d_in, const int* in_sizes, int n_in,
                              void* d_out, int out_size) {
    const float* x  = (const float*)d_in[0];
    const float* ew = (const float*)d_in[1];
    const float* W1 = (const float*)d_in[2];
    const float* b1 = (const float*)d_in[3];
    const float* W2 = (const float*)d_in[4];
    const float* b2 = (const float*)d_in[5];
    const float* Wm = (const float*)d_in[6];
    const float* bm = (const float*)d_in[7];
    const int*   ei = (const int*)d_in[8];

    int Nn = in_sizes[0] / DIM;
    int E  = in_sizes[1];
    const int* src = ei;
    const int* dst = ei + E;
    float* out = (float*)d_out;

    __half *t_buf, *a_buf, *w1_buf, *w2_buf;
    cudaGetSymbolAddress((void**)&t_buf, g_t);
    cudaGetSymbolAddress((void**)&a_buf, g_a);
    cudaGetSymbolAddress((void**)&w1_buf, g_w1);
    cudaGetSymbolAddress((void**)&w2_buf, g_w2);

    cudaFuncSetAttribute(k_mma1, cudaFuncAttributeMaxDynamicSharedMemorySize, SMEM_MMA);
    cudaFuncSetAttribute(k_mma,  cudaFuncAttributeMaxDynamicSharedMemorySize, SMEM_MMA);

    int CA = (Nn * DIM) / 2048;            // convA blocks (1536)
    int FB = E / 1024;                     // fill blocks (384)

    // prologue: state-zero + convW1 + convA
    k_mega<<<44 + CA, 256>>>(x, W1);
    // layer 1 GEMM + (overlapped) bucket fill + convW2
    k_mma1<<<NTILES + FB + 32, 256, SMEM_MMA>>>(a_buf, w1_buf, t_buf,
                                                src, dst, ew, W2, FB);
    k_agg1<<<Nn / 8, 256>>>(t_buf, b1, a_buf);
    // layer 2 GEMM
    k_mma<<<NTILES, 256, SMEM_MMA>>>(a_buf, w2_buf, t_buf);
    k_aggmlp<<<Nn / 16, 512>>>(t_buf, b2, Wm, bm, out, out + (out_size - 1), Nn);
}